// round 12
// baseline (speedup 1.0000x reference)
#include <cuda_runtime.h>
#include <cstdint>

// ---------------- problem constants ----------------
#define USERN 100000
#define ITEMN 50000
#define TAGN  20000
#define NN (USERN + ITEMN)   // 150000 interaction-graph nodes
#define MM (ITEMN + TAGN)    // 70000 tag-graph nodes
#define DD 64
#define Q4 16                // float4 per embedding row
#define E_ADJ 2000000
#define E_TAG 1000000
#define E_SOC 1000000

// ---------------- device scratch (no allocs allowed) ----------------
__device__ float g_lat[NN * DD];
__device__ float g_taglat[MM * DD];
__device__ float g_tem[NN * DD];     // adj-graph accumulator
__device__ float g_tg[MM * DD];      // tag-graph accumulator
__device__ float g_soc[USERN * DD];  // social-graph accumulator
__device__ float g_wadj[E_ADJ];
__device__ float g_wtag[E_TAG];
__device__ float g_wsoc[E_SOC];

// ---------------- threefry-2x32 (exact JAX implementation) ----------------
__host__ __device__ __forceinline__ void tf2x32(uint32_t k0, uint32_t k1,
                                                uint32_t x0, uint32_t x1,
                                                uint32_t& o0, uint32_t& o1) {
    uint32_t ks2 = k0 ^ k1 ^ 0x1BD11BDAu;
    x0 += k0; x1 += k1;
#define TF_RR(r) { x0 += x1; x1 = (x1 << (r)) | (x1 >> (32 - (r))); x1 ^= x0; }
    TF_RR(13) TF_RR(15) TF_RR(26) TF_RR(6)   x0 += k1;  x1 += ks2 + 1u;
    TF_RR(17) TF_RR(29) TF_RR(16) TF_RR(24)  x0 += ks2; x1 += k0 + 2u;
    TF_RR(13) TF_RR(15) TF_RR(26) TF_RR(6)   x0 += k0;  x1 += k1 + 3u;
    TF_RR(17) TF_RR(29) TF_RR(16) TF_RR(24)  x0 += k1;  x1 += ks2 + 4u;
    TF_RR(13) TF_RR(15) TF_RR(26) TF_RR(6)   x0 += ks2; x1 += k0 + 5u;
#undef TF_RR
    o0 = x0; o1 = x1;
}

// ---------------- kernels ----------------
__global__ void init_kernel(const float4* __restrict__ uE,
                            const float4* __restrict__ iE,
                            const float4* __restrict__ tE,
                            float4* __restrict__ out) {
    int t = blockIdx.x * blockDim.x + threadIdx.x;
    float4 z = make_float4(0.f, 0.f, 0.f, 0.f);
    if (t < NN * Q4) {
        float4 v = (t < USERN * Q4) ? uE[t] : iE[t - USERN * Q4];
        reinterpret_cast<float4*>(g_lat)[t] = v;
        out[t] = v;                                    // acc starts at lat
        reinterpret_cast<float4*>(g_tem)[t] = z;
    }
    if (t < MM * Q4) {
        float4 v = (t < ITEMN * Q4) ? iE[t] : tE[t - ITEMN * Q4];
        reinterpret_cast<float4*>(g_taglat)[t] = v;
        reinterpret_cast<float4*>(g_tg)[t] = z;
    }
    if (t < USERN * Q4) reinterpret_cast<float4*>(g_soc)[t] = z;
}

// Per-edge dropout weight, matching JAX with jax_threefry_partitionable=True
// (default in modern JAX): for element e, counter pair is (hi=0, lo=e) and the
// 32-bit random word is the XOR-fold of the two threefry output lanes.
// uniform = bitcast((bits>>9)|0x3f800000) - 1; mask = floor(u + KEEP);
// weight = vals * mask * (1/KEEP). All bit-exact vs the reference.
template <int W>
__global__ void weights_kernel(const float* __restrict__ vals, int E,
                               uint32_t k0, uint32_t k1) {
    int e = blockIdx.x * blockDim.x + threadIdx.x;
    if (e >= E) return;
    float* w = (W == 0) ? g_wadj : (W == 1) ? g_wtag : g_wsoc;
    uint32_t o0, o1;
    tf2x32(k0, k1, 0u, (uint32_t)e, o0, o1);
    uint32_t bits = o0 ^ o1;
    const float INVKEEP = (float)(1.0 / 0.9);
    float u = __uint_as_float((bits >> 9) | 0x3f800000u) - 1.0f;
    float m = floorf(u + 0.9f);   // 0 or 1, bit-exact vs jnp.floor(u + KEEP)
    w[e] = vals[e] * m * INVKEEP;
}

// 16 threads per edge: one float4 gather + one red.global.add.v4.f32 each.
// MODE 0: adj (src g_lat,   dst g_tem)
// MODE 1: tag (src lat[USER+c] if c<ITEM else taglat[c], dst g_tg)
// MODE 2: soc (src g_lat,   dst g_soc)
template <int MODE>
__global__ void scatter_kernel(const int* __restrict__ rows,
                               const int* __restrict__ cols, int E) {
    int t = blockIdx.x * blockDim.x + threadIdx.x;
    int e = t >> 4;
    if (e >= E) return;
    int q = t & 15;
    const float* w = (MODE == 0) ? g_wadj : (MODE == 1) ? g_wtag : g_wsoc;
    float we = __ldg(w + e);
    if (we == 0.0f) return;   // dropped edge: whole 16-lane group skips together
    int col = __ldg(cols + e);
    int row = __ldg(rows + e);
    const float4* src;
    if (MODE == 1) {
        src = (col < ITEMN)
                  ? reinterpret_cast<const float4*>(g_lat) + (size_t)(USERN + col) * Q4
                  : reinterpret_cast<const float4*>(g_taglat) + (size_t)col * Q4;
    } else {
        src = reinterpret_cast<const float4*>(g_lat) + (size_t)col * Q4;
    }
    float* dstf = (MODE == 0) ? g_tem : (MODE == 1) ? g_tg : g_soc;
    float4 v = src[q];
    float4 a = make_float4(v.x * we, v.y * we, v.z * we, v.w * we);
    float4* dp = reinterpret_cast<float4*>(dstf) + (size_t)row * Q4 + q;
    asm volatile("red.global.add.v4.f32 [%0], {%1,%2,%3,%4};"
                 :: "l"(dp), "f"(a.x), "f"(a.y), "f"(a.z), "f"(a.w)
                 : "memory");
}

__device__ __forceinline__ float lk(float x) { return x >= 0.f ? x : 0.5f * x; }
__device__ __forceinline__ float4 lk4(float4 h) {
    return make_float4(lk(h.x), lk(h.y), lk(h.z), lk(h.w));
}

// LeakyReLU + merge + acc update + in-place zeroing of tem/soc (each element
// touched by exactly one thread). g_tg is only READ here (two reader ranges),
// re-zeroed by zero_tg_kernel afterwards.
__global__ void combine_kernel(float4* __restrict__ out) {
    int t = blockIdx.x * blockDim.x + threadIdx.x;
    float4 z = make_float4(0.f, 0.f, 0.f, 0.f);
    if (t < NN * Q4) {
        float4 h = reinterpret_cast<float4*>(g_tem)[t];
        reinterpret_cast<float4*>(g_tem)[t] = z;
        float4 o = lk4(h);
        if (t < USERN * Q4) {
            float4 s = lk4(reinterpret_cast<float4*>(g_soc)[t]);
            reinterpret_cast<float4*>(g_soc)[t] = z;
            o.x += s.x; o.y += s.y; o.z += s.z; o.w += s.w;
        } else {
            float4 g = lk4(reinterpret_cast<float4*>(g_tg)[t - USERN * Q4]);
            o.x += g.x; o.y += g.y; o.z += g.z; o.w += g.w;
        }
        reinterpret_cast<float4*>(g_lat)[t] = o;
        float4 a = out[t];
        out[t] = make_float4(a.x + o.x, a.y + o.y, a.z + o.z, a.w + o.w);
    }
    if (t < MM * Q4) {
        reinterpret_cast<float4*>(g_taglat)[t] =
            lk4(reinterpret_cast<float4*>(g_tg)[t]);
    }
}

__global__ void zero_tg_kernel() {
    int t = blockIdx.x * blockDim.x + threadIdx.x;
    if (t < MM * Q4)
        reinterpret_cast<float4*>(g_tg)[t] = make_float4(0.f, 0.f, 0.f, 0.f);
}

// ---------------- launch ----------------
extern "C" void kernel_launch(void* const* d_in, const int* in_sizes, int n_in,
                              void* d_out, int out_size) {
    const float4* uE   = (const float4*)d_in[0];
    const float4* iE   = (const float4*)d_in[1];
    const float4* tE   = (const float4*)d_in[2];
    const int*   adj_r = (const int*)d_in[3];
    const int*   adj_c = (const int*)d_in[4];
    const float* adj_v = (const float*)d_in[5];
    const int*   tag_r = (const int*)d_in[6];
    const int*   tag_c = (const int*)d_in[7];
    const float* tag_v = (const float*)d_in[8];
    const int*   soc_r = (const int*)d_in[9];
    const int*   soc_c = (const int*)d_in[10];
    const float* soc_v = (const float*)d_in[11];
    float4* out = (float4*)d_out;

    const int T = 256;
    const int TS = 512;   // scatter kernels: fewer blocks, same per-thread work
    auto cdiv = [](long long a, long long b) { return (int)((a + b - 1) / b); };

    init_kernel<<<cdiv((long long)NN * Q4, T), T>>>(uE, iE, tE, out);

    // Fold dropout keys on the host: key(42) = (0, 42); fold_in(key, d) =
    // threefry_2x32(key, (0, d)).  (fold_in is NOT affected by the
    // threefry_partitionable flag — only random_bits is.)
    uint32_t kk[6][2];
    for (int d = 0; d < 6; ++d)
        tf2x32(0u, 42u, 0u, (uint32_t)d, kk[d][0], kk[d][1]);

    for (int L = 0; L < 2; ++L) {
        weights_kernel<0><<<cdiv(E_ADJ, T), T>>>(adj_v, E_ADJ,
                                                 kk[3 * L][0], kk[3 * L][1]);
        weights_kernel<1><<<cdiv(E_TAG, T), T>>>(tag_v, E_TAG,
                                                 kk[3 * L + 1][0], kk[3 * L + 1][1]);
        weights_kernel<2><<<cdiv(E_SOC, T), T>>>(soc_v, E_SOC,
                                                 kk[3 * L + 2][0], kk[3 * L + 2][1]);
        scatter_kernel<0><<<cdiv((long long)E_ADJ * 16, TS), TS>>>(adj_r, adj_c, E_ADJ);
        scatter_kernel<1><<<cdiv((long long)E_TAG * 16, TS), TS>>>(tag_r, tag_c, E_TAG);
        scatter_kernel<2><<<cdiv((long long)E_SOC * 16, TS), TS>>>(soc_r, soc_c, E_SOC);
        combine_kernel<<<cdiv((long long)NN * Q4, T), T>>>(out);
        if (L == 0) zero_tg_kernel<<<cdiv((long long)MM * Q4, T), T>>>();
    }
}